// round 17
// baseline (speedup 1.0000x reference)
#include <cuda_runtime.h>
#include <cuda_fp16.h>
#include <cstdint>

#define C_CH 32
#define DIM  128
#define NK   27
#define VOL_ELEMS (C_CH * DIM * DIM * DIM)
#define NCELL 4096            // 16x16x16 cells of 8^3 voxels
#define PERM_MAX (1 << 18)
#define TPW 16                // vertices per tile

#define ROWB 80               // bytes per feat row (16 fp16 padded to 80B)
#define WFEAT (16 * ROWB)     // 1280B per warp feat tile
#define GB_WORDS (NK * 512)   // pre-packed B-fragment words (13824)

// slab ends (cz<K tiles sample z <= 8K+3.97, need slab end >= 8K+5)
#define ZA 32                 // covers cz<3  (max z 28.0)
#define ZB 56                 // covers cz<6  (max z 52.0)
#define ZC 88                 // covers cz<10 (max z 84.0)

// Scratch (device globals: allocation-free per harness rules)
__device__ __half g_volh[VOL_ELEMS];          // channel-last fp16 volume
__device__ float g_G[NK * C_CH * C_CH];       // [k][c][o] folded weights (fp32)
__device__ unsigned g_Gb[GB_WORDS];           // fp16 B-frags, paired lane layout
__device__ float g_bias[C_CH];
__device__ int   g_hist[NCELL];
__device__ int   g_base[NCELL];
__device__ int   g_perm[PERM_MAX];
__device__ int   g_pb[3];                     // vertex counts: cz<3, cz<6, cz<10

// neighbour shifts pre-scaled to pixel space: {-1,0,1} * 0.0625 * 63.5
#define M1 -3.96875f
#define P1  3.96875f
#define Z0  0.0f
__constant__ float c_shx[NK] = {M1,M1,M1,M1,M1,M1,M1,M1,M1,
                                Z0,Z0,Z0,Z0,Z0,Z0,Z0,Z0,Z0,
                                P1,P1,P1,P1,P1,P1,P1,P1,P1};
__constant__ float c_shy[NK] = {M1,M1,M1,Z0,Z0,Z0,P1,P1,P1,
                                M1,M1,M1,Z0,Z0,Z0,P1,P1,P1,
                                M1,M1,M1,Z0,Z0,Z0,P1,P1,P1};
__constant__ float c_shz[NK] = {M1,Z0,P1,M1,Z0,P1,M1,Z0,P1,
                                M1,Z0,P1,M1,Z0,P1,M1,Z0,P1,
                                M1,Z0,P1,M1,Z0,P1,M1,Z0,P1};

// ---------------------------------------------------------------------------
// Prep 1 (27 blocks): M[k][j][o] = sum_c conv_w[o,c,k]*Wd[c,j]
// ---------------------------------------------------------------------------
__global__ __launch_bounds__(1024) void prep1_kernel(
    const float* __restrict__ w_d1, const float* __restrict__ w_d2,
    const float* __restrict__ conv_w)
{
    __shared__ float Wds[1024];    // Wd[c][j]
    __shared__ float convs[1024];  // conv[c][o] for this k
    const int tid = threadIdx.x, k = blockIdx.x;
    const int o = tid & 31, j = tid >> 5;

    {   // Wd = w_d2 @ w_d1
        float s = 0.f;
        #pragma unroll
        for (int m = 0; m < 32; m++)
            s += w_d2[(tid >> 5) * 32 + m] * w_d1[m * 32 + (tid & 31)];
        Wds[tid] = s;
    }
    convs[tid] = conv_w[(o * 32 + (tid >> 5)) * 27 + k];
    __syncthreads();

    float acc = 0.f;
    #pragma unroll
    for (int c = 0; c < 32; c++)
        acc += convs[c * 32 + o] * Wds[c * 32 + j];
    g_G[k * 1024 + j * 32 + o] = acc;
}

// ---------------------------------------------------------------------------
// Prep 2 (1 block): center-tap correction on k=13 + fused bias.
// ---------------------------------------------------------------------------
__global__ __launch_bounds__(1024) void prep2_kernel(
    const float* __restrict__ w_d2, const float* __restrict__ b_d1,
    const float* __restrict__ b_d2,
    const float* __restrict__ w_c1, const float* __restrict__ b_c1,
    const float* __restrict__ w_c2, const float* __restrict__ b_c2,
    const float* __restrict__ conv_w, const float* __restrict__ conv_b)
{
    __shared__ float Wcs[1024], part[1024], bds[32], bcs[32];
    const int tid = threadIdx.x;
    const int o = tid & 31, j = tid >> 5;

    {   // Wc = w_c2 @ w_c1
        float s = 0.f;
        #pragma unroll
        for (int m = 0; m < 32; m++)
            s += w_c2[(tid >> 5) * 32 + m] * w_c1[m * 32 + (tid & 31)];
        Wcs[tid] = s;
    }
    if (tid < 32) {
        float sd = 0.f, sc = 0.f;
        #pragma unroll
        for (int m = 0; m < 32; m++) {
            sd += w_d2[tid * 32 + m] * b_d1[m];
            sc += w_c2[tid * 32 + m] * b_c1[m];
        }
        bds[tid] = sd + b_d2[tid];
        bcs[tid] = sc + b_c2[tid];
    }
    float rs = 0.f;
    #pragma unroll
    for (int k = 0; k < NK; k++)
        rs += conv_w[(o * 32 + j) * 27 + k];
    __syncthreads();

    part[j * 32 + o] = bds[j] * rs;

    float S = 0.f;
    #pragma unroll
    for (int k = 0; k < NK; k++) S += g_G[k * 1024 + tid];
    g_G[13 * 1024 + tid] += Wcs[o * 32 + j] - S;
    __syncthreads();

    if (tid < 32) {
        float a = 0.f;
        #pragma unroll
        for (int c = 0; c < 32; c++) a += part[c * 32 + tid];
        g_bias[tid] = a + conv_b[tid] + bcs[tid];
    }
}

// ---------------------------------------------------------------------------
// Pack (27 blocks, one per k): fp16 B-fragments, paired lane layout.
// ---------------------------------------------------------------------------
__global__ __launch_bounds__(512) void pack_kernel()
{
    __shared__ float Gs[1024];
    const int k = blockIdx.x, tid = threadIdx.x;
    Gs[tid]       = g_G[k * 1024 + tid];
    Gs[tid + 512] = g_G[k * 1024 + tid + 512];
    __syncthreads();

    const int e  = tid;
    const int ks = e >> 8;
    const int nt = (e >> 6) & 3;
    const int l  = (e >> 1) & 31;
    const int r  = e & 1;
    const int c  = 16 * ks + 8 * r + 2 * (l & 3);
    const int oo = 8 * nt + (l >> 2);
    __half2 h = __floats2half2_rn(Gs[c * 32 + oo], Gs[(c + 1) * 32 + oo]);
    g_Gb[k * 512 + e] = *reinterpret_cast<unsigned*>(&h);
}

// ---------------------------------------------------------------------------
// Transpose + convert a z-slab: [C][D][H][W] fp32 -> channel-last fp16.
// ---------------------------------------------------------------------------
__global__ __launch_bounds__(256) void transpose_kernel(
    const float* __restrict__ vin, int z0)
{
    __shared__ float tile[32][33];
    const int x0 = blockIdx.x * 32;
    const int y = blockIdx.y, z = blockIdx.z + z0;
    const int tid = threadIdx.x;
    const int tx = tid & 31, ty = tid >> 5;

    #pragma unroll
    for (int i = 0; i < 4; i++) {
        const int c = ty + 8 * i;
        tile[c][tx] = vin[(((size_t)c * DIM + z) * DIM + y) * DIM + x0 + tx];
    }
    __syncthreads();

    const int g  = tid & 7;          // channel quad (4 halves = 8B)
    const int xx = tid >> 3;         // x within tile (0..31)
    const size_t obase = ((size_t)z * DIM + y) * DIM + x0;

    __half2 h01 = __floats2half2_rn(tile[4 * g + 0][xx], tile[4 * g + 1][xx]);
    __half2 h23 = __floats2half2_rn(tile[4 * g + 2][xx], tile[4 * g + 3][xx]);
    uint2 u;
    u.x = *reinterpret_cast<unsigned*>(&h01);
    u.y = *reinterpret_cast<unsigned*>(&h23);
    reinterpret_cast<uint2*>(g_volh + (obase + xx) * C_CH)[g] = u;
}

// ---------------------------------------------------------------------------
// Vertex binning: count -> scan (also phase bounds) -> scatter.
// ---------------------------------------------------------------------------
__device__ __forceinline__ int cell_of(float x, float y, float z)
{
    float px = fminf(fmaxf((x + 1.f) * 63.5f, 0.f), 127.f);
    float py = fminf(fmaxf((y + 1.f) * 63.5f, 0.f), 127.f);
    float pz = fminf(fmaxf((z + 1.f) * 63.5f, 0.f), 127.f);
    const int cx = ((int)px) >> 3, cy = ((int)py) >> 3, cz = ((int)pz) >> 3;
    return (cz << 8) | (cy << 4) | cx;
}

__global__ void count_kernel(const float* __restrict__ verts, int Ntot)
{
    const int n = blockIdx.x * blockDim.x + threadIdx.x;
    if (n >= Ntot) return;
    atomicAdd(&g_hist[cell_of(verts[3 * n], verts[3 * n + 1], verts[3 * n + 2])], 1);
}

__global__ __launch_bounds__(1024) void scan_kernel()
{
    __shared__ int sh[1024];
    const int t = threadIdx.x;
    int h0 = g_hist[4 * t], h1 = g_hist[4 * t + 1],
        h2 = g_hist[4 * t + 2], h3 = g_hist[4 * t + 3];
    const int mysum = h0 + h1 + h2 + h3;
    sh[t] = mysum;
    __syncthreads();
    for (int off = 1; off < 1024; off <<= 1) {
        int v = (t >= off) ? sh[t - off] : 0;
        __syncthreads();
        sh[t] += v;
        __syncthreads();
    }
    int e = sh[t] - mysum;
    g_base[4 * t]     = e;
    g_base[4 * t + 1] = e + h0;
    g_base[4 * t + 2] = e + h0 + h1;
    g_base[4 * t + 3] = e + h0 + h1 + h2;
    // phase bounds (inclusive prefix): cz<3 = cells<768 -> groups 0..191;
    // cz<6 = cells<1536 -> sh[383]; cz<10 = cells<2560 -> sh[639].
    if (t == 191) g_pb[0] = sh[191];
    if (t == 383) g_pb[1] = sh[383];
    if (t == 639) g_pb[2] = sh[639];
}

__global__ void scatter_kernel(const float* __restrict__ verts, int Ntot)
{
    const int n = blockIdx.x * blockDim.x + threadIdx.x;
    if (n >= Ntot) return;
    const int c = cell_of(verts[3 * n], verts[3 * n + 1], verts[3 * n + 2]);
    const int pos = atomicAdd(&g_base[c], 1);
    g_perm[pos] = n;
}

// ---------------------------------------------------------------------------
__device__ __forceinline__ __half2 u2h(unsigned u)
{
    return *reinterpret_cast<__half2*>(&u);
}

__device__ __forceinline__ void mma_16816(
    float* d, unsigned a0, unsigned a1, unsigned a2, unsigned a3,
    unsigned b0, unsigned b1)
{
    asm volatile(
        "mma.sync.aligned.m16n8k16.row.col.f32.f16.f16.f32 "
        "{%0,%1,%2,%3}, {%4,%5,%6,%7}, {%8,%9}, {%0,%1,%2,%3};"
        : "+f"(d[0]), "+f"(d[1]), "+f"(d[2]), "+f"(d[3])
        : "r"(a0), "r"(a1), "r"(a2), "r"(a3), "r"(b0), "r"(b1));
}

// ---------------------------------------------------------------------------
// Fused sample + tensor-core GEMM, 2-way split-K, phased by CONTIGUOUS tile
// ranges (perm is z-major sorted): phase p covers tiles [bounds[p],bounds[p+1])
// with bounds = {0, pb0/16, pb1/16, pb2/16, nTiles}.
// ---------------------------------------------------------------------------
__global__ __launch_bounds__(256, 3) void main_kernel(
    const float* __restrict__ verts, float* __restrict__ out, int Ntot,
    int phase)
{
    const int nTiles = (Ntot + TPW - 1) / TPW;
    const int b0 = g_pb[0] >> 4, b1 = g_pb[1] >> 4, b2 = g_pb[2] >> 4;
    const int lo = (phase == 0) ? 0  : (phase == 1) ? b0 : (phase == 2) ? b1 : b2;
    const int hi = (phase == 0) ? b0 : (phase == 1) ? b1 : (phase == 2) ? b2 : nTiles;

    const int tbase = blockIdx.x * 4;
    if (tbase >= hi || tbase + 3 < lo) return;   // whole block dead

    __shared__ __align__(16) unsigned char feats[8 * WFEAT];
    __shared__ float partial[4 * 16 * 32];      // [tib][q][lane]
    const int warp = threadIdx.x >> 5, lane = threadIdx.x & 31;
    const int tib = warp >> 1, khalf = warp & 1;
    const int tile = tbase + tib;
    const bool live = (tile >= lo) && (tile < hi);

    const int n0 = tile * TPW;
    const int v = lane & 15;
    const int idx = n0 + v;
    const bool valid = live && (idx < Ntot);
    const int n = valid ? g_perm[idx] : 0;

    float px0 = 0.f, py0 = 0.f, pz0 = 0.f;   // hoisted pixel-space coords
    if (valid) {
        px0 = fmaf(verts[3 * n + 0], 63.5f, 63.5f);
        py0 = fmaf(verts[3 * n + 1], 63.5f, 63.5f);
        pz0 = fmaf(verts[3 * n + 2], 63.5f, 63.5f);
    }

    const int c4 = lane & 7;              // channel quad
    const int v4 = lane >> 3;             // vertex within group of 4

    unsigned char* fb = feats + warp * WFEAT;
    const unsigned fb_s = (unsigned)__cvta_generic_to_shared(fb);

    const int lg = lane >> 3;
    const unsigned arow = (lane & 7) + ((lg & 1) << 3);
    const unsigned lm0 = fb_s + arow * ROWB + ((lg >> 1) << 4);  // ks=0
    const unsigned lm1 = lm0 + 32;                                // ks=1

    float d[4][4];
    #pragma unroll
    for (int i = 0; i < 4; i++)
        #pragma unroll
        for (int q = 0; q < 4; q++) d[i][q] = 0.f;

    const int k0 = khalf ? 14 : 0;
    const int k1 = khalf ? NK : 14;

    if (live) {
        #pragma unroll 1
        for (int k = k0; k < k1; k++) {
            float px = fminf(fmaxf(px0 + c_shx[k], 0.f), 127.f);
            float py = fminf(fmaxf(py0 + c_shy[k], 0.f), 127.f);
            float pz = fminf(fmaxf(pz0 + c_shz[k], 0.f), 127.f);
            const float fx = floorf(px), fy = floorf(py), fz = floorf(pz);
            const int ix = (int)fx, iy = (int)fy, iz = (int)fz;
            const float wx = px - fx, wy = py - fy, wz = pz - fz;
            // uint2 index of voxel (multiple of 8) with step flags packed in
            // the low 3 bits: bit0 x+1 valid, bit1 y+1 valid, bit2 z+1 valid.
            const int bidx = (iz * (DIM * DIM * C_CH >> 2)) +
                             (iy * (DIM * C_CH >> 2)) + (ix * (C_CH >> 2));
            const int pk = bidx | ((ix < DIM - 1) ? 1 : 0)
                                | ((iy < DIM - 1) ? 2 : 0)
                                | ((iz < DIM - 1) ? 4 : 0);

            #pragma unroll
            for (int g4 = 0; g4 < 4; g4++) {
                const int src = g4 * 4 + v4;
                const int pkv = __shfl_sync(0xffffffffu, pk, src);
                const float wxv = __shfl_sync(0xffffffffu, wx, src);
                const float wyv = __shfl_sync(0xffffffffu, wy, src);
                const float wzv = __shfl_sync(0xffffffffu, wz, src);
                const int b   = pkv & ~7;
                const int sx4 = (pkv & 1) ? (C_CH >> 2) : 0;
                const int sy4 = (pkv & 2) ? (DIM * C_CH >> 2) : 0;
                const int sz4 = (pkv & 4) ? (DIM * DIM * C_CH >> 2) : 0;

                const uint2* p = reinterpret_cast<const uint2*>(g_volh) + b + c4;
                const uint2 u000 = __ldg(p);
                const uint2 u001 = __ldg(p + sx4);
                const uint2 u010 = __ldg(p + sy4);
                const uint2 u011 = __ldg(p + sy4 + sx4);
                const uint2 u100 = __ldg(p + sz4);
                const uint2 u101 = __ldg(p + sz4 + sx4);
                const uint2 u110 = __ldg(p + sz4 + sy4);
                const uint2 u111 = __ldg(p + sz4 + sy4 + sx4);

                // corner weights in fp32, splat-packed to half2 (1 cvt each)
                const float ax0 = 1.f - wxv, ay0 = 1.f - wyv, az0 = 1.f - wzv;
                const float c00 = az0 * ay0, c01 = az0 * wyv;
                const float c10 = wzv * ay0, c11 = wzv * wyv;
                const __half2 h000 = __floats2half2_rn(c00 * ax0, c00 * ax0);
                const __half2 h001 = __floats2half2_rn(c00 * wxv, c00 * wxv);
                const __half2 h010 = __floats2half2_rn(c01 * ax0, c01 * ax0);
                const __half2 h011 = __floats2half2_rn(c01 * wxv, c01 * wxv);
                const __half2 h100 = __floats2half2_rn(c10 * ax0, c10 * ax0);
                const __half2 h101 = __floats2half2_rn(c10 * wxv, c10 * wxv);
                const __half2 h110 = __floats2half2_rn(c11 * ax0, c11 * ax0);
                const __half2 h111 = __floats2half2_rn(c11 * wxv, c11 * wxv);

                // trilinear entirely in fp16: two z-partials + final add
                __half2 paX = __hmul2(h000, u2h(u000.x));
                paX = __hfma2(h001, u2h(u001.x), paX);
                paX = __hfma2(h010, u2h(u010.x), paX);
                paX = __hfma2(h011, u2h(u011.x), paX);
                __half2 pbX = __hmul2(h100, u2h(u100.x));
                pbX = __hfma2(h101, u2h(u101.x), pbX);
                pbX = __hfma2(h110, u2h(u110.x), pbX);
                pbX = __hfma2(h111, u2h(u111.x), pbX);
                __half2 rX = __hadd2(paX, pbX);

                __half2 paY = __hmul2(h000, u2h(u000.y));
                paY = __hfma2(h001, u2h(u001.y), paY);
                paY = __hfma2(h010, u2h(u010.y), paY);
                paY = __hfma2(h011, u2h(u011.y), paY);
                __half2 pbY = __hmul2(h100, u2h(u100.y));
                pbY = __hfma2(h101, u2h(u101.y), pbY);
                pbY = __hfma2(h110, u2h(u110.y), pbY);
                pbY = __hfma2(h111, u2h(u111.y), pbY);
                __half2 rY = __hadd2(paY, pbY);

                uint2 u;
                u.x = *reinterpret_cast<unsigned*>(&rX);
                u.y = *reinterpret_cast<unsigned*>(&rY);
                *reinterpret_cast<uint2*>(fb + src * ROWB + c4 * 8) = u;
            }
            __syncwarp();

            unsigned a0, a1, a2, a3, a4, a5, a6, a7;
            asm volatile("ldmatrix.sync.aligned.m8n8.x4.shared.b16 {%0,%1,%2,%3}, [%4];"
                         : "=r"(a0), "=r"(a1), "=r"(a2), "=r"(a3) : "r"(lm0) : "memory");
            asm volatile("ldmatrix.sync.aligned.m8n8.x4.shared.b16 {%0,%1,%2,%3}, [%4];"
                         : "=r"(a4), "=r"(a5), "=r"(a6), "=r"(a7) : "r"(lm1) : "memory");

            // paired B fragments: LDG.64, coalesced
            const uint2* gb2 = reinterpret_cast<const uint2*>(g_Gb) +
                               k * 256 + lane;
            #pragma unroll
            for (int nt = 0; nt < 4; nt++) {
                const uint2 b01 = __ldg(gb2 + nt * 32);
                mma_16816(d[nt], a0, a1, a2, a3, b01.x, b01.y);
            }
            #pragma unroll
            for (int nt = 0; nt < 4; nt++) {
                const uint2 b01 = __ldg(gb2 + 128 + nt * 32);
                mma_16816(d[nt], a4, a5, a6, a7, b01.x, b01.y);
            }
            __syncwarp();
        }
    }

    // split-K combine: khalf=1 publishes, khalf=0 reduces + stores
    if (live && khalf) {
        #pragma unroll
        for (int nt = 0; nt < 4; nt++)
            #pragma unroll
            for (int q = 0; q < 4; q++)
                partial[tib * 512 + (nt * 4 + q) * 32 + lane] = d[nt][q];
    }
    __syncthreads();
    if (live && !khalf) {
        #pragma unroll
        for (int nt = 0; nt < 4; nt++)
            #pragma unroll
            for (int q = 0; q < 4; q++)
                d[nt][q] += partial[tib * 512 + (nt * 4 + q) * 32 + lane];

        const int r0 = lane >> 2;
        const int cb = 2 * (lane & 3);
        const int i0 = n0 + r0, i1 = i0 + 8;
        const int p0 = (i0 < Ntot) ? g_perm[i0] : -1;
        const int p1 = (i1 < Ntot) ? g_perm[i1] : -1;

        #pragma unroll
        for (int nt = 0; nt < 4; nt++) {
            const int col = 8 * nt + cb;
            const float blo = __ldg(&g_bias[col]);
            const float bhi = __ldg(&g_bias[col + 1]);
            if (p0 >= 0) {
                float2 w0 = make_float2(d[nt][0] + blo, d[nt][1] + bhi);
                *reinterpret_cast<float2*>(out + p0 * C_CH + col) = w0;
            }
            if (p1 >= 0) {
                float2 w1 = make_float2(d[nt][2] + blo, d[nt][3] + bhi);
                *reinterpret_cast<float2*>(out + p1 * C_CH + col) = w1;
            }
        }
    }
}

// ---------------------------------------------------------------------------
// Graph topology (3 side streams, 4 phases — phase 2 chained on s_prep):
//   stream 0 : Ta[0,32) -> Tb[32,56) -> Tc[56,88) -> Td[88,128) -> main(ph3)
//   s_mainA  : waits {Ta, prep, bin} -> main(ph0)
//   s_bin    : binning -> waits {Tb, prep} -> main(ph1)
//   s_prep   : prep1->prep2->pack -> waits {Tc, bin} -> main(ph2)
// ---------------------------------------------------------------------------
extern "C" void kernel_launch(void* const* d_in, const int* in_sizes, int n_in,
                              void* d_out, int out_size)
{
    const float* voxel = (const float*)d_in[0];
    const float* verts = (const float*)d_in[1];
    const int Ntot = in_sizes[1] / 3;

    static cudaStream_t s_prep = nullptr, s_bin = nullptr, s_mainA = nullptr;
    static cudaEvent_t e_fork, e_prep, e_bin, e_Ta, e_Tb, e_Tc, e_mA, e_mB, e_mC;
    static void* hist_ptr = nullptr;
    static void* base_ptr = nullptr;
    if (!s_prep) {
        cudaStreamCreateWithFlags(&s_prep, cudaStreamNonBlocking);
        cudaStreamCreateWithFlags(&s_bin, cudaStreamNonBlocking);
        cudaStreamCreateWithFlags(&s_mainA, cudaStreamNonBlocking);
        cudaEventCreateWithFlags(&e_fork, cudaEventDisableTiming);
        cudaEventCreateWithFlags(&e_prep, cudaEventDisableTiming);
        cudaEventCreateWithFlags(&e_bin, cudaEventDisableTiming);
        cudaEventCreateWithFlags(&e_Ta, cudaEventDisableTiming);
        cudaEventCreateWithFlags(&e_Tb, cudaEventDisableTiming);
        cudaEventCreateWithFlags(&e_Tc, cudaEventDisableTiming);
        cudaEventCreateWithFlags(&e_mA, cudaEventDisableTiming);
        cudaEventCreateWithFlags(&e_mB, cudaEventDisableTiming);
        cudaEventCreateWithFlags(&e_mC, cudaEventDisableTiming);
        cudaGetSymbolAddress(&hist_ptr, g_hist);
        cudaGetSymbolAddress(&base_ptr, g_base);
    }

    const int nTiles = (Ntot + TPW - 1) / TPW;
    const int blocks = (nTiles + 3) / 4;

    // fork
    cudaEventRecord(e_fork, 0);
    cudaStreamWaitEvent(s_prep, e_fork, 0);
    cudaStreamWaitEvent(s_bin, e_fork, 0);

    // stream 0: transpose in four z-slabs
    {
        dim3 tb(256);
        dim3 tga(DIM / 32, DIM, ZA);
        transpose_kernel<<<tga, tb>>>(voxel, 0);
        cudaEventRecord(e_Ta, 0);
        dim3 tgb(DIM / 32, DIM, ZB - ZA);
        transpose_kernel<<<tgb, tb>>>(voxel, ZA);
        cudaEventRecord(e_Tb, 0);
        dim3 tgc(DIM / 32, DIM, ZC - ZB);
        transpose_kernel<<<tgc, tb>>>(voxel, ZB);
        cudaEventRecord(e_Tc, 0);
        dim3 tgd(DIM / 32, DIM, DIM - ZC);
        transpose_kernel<<<tgd, tb>>>(voxel, ZC);
    }

    // s_prep: weight folding + parallel pack
    prep1_kernel<<<27, 1024, 0, s_prep>>>(
        (const float*)d_in[2], (const float*)d_in[4], (const float*)d_in[10]);
    prep2_kernel<<<1, 1024, 0, s_prep>>>(
        (const float*)d_in[4], (const float*)d_in[3], (const float*)d_in[5],
        (const float*)d_in[6], (const float*)d_in[7], (const float*)d_in[8],
        (const float*)d_in[9], (const float*)d_in[10], (const float*)d_in[11]);
    pack_kernel<<<27, 512, 0, s_prep>>>();
    cudaEventRecord(e_prep, s_prep);

    // s_bin: vertex spatial binning
    cudaMemsetAsync(hist_ptr, 0, NCELL * sizeof(int), s_bin);
    cudaMemsetAsync(base_ptr, 0, NCELL * sizeof(int), s_bin);
    count_kernel<<<(Ntot + 255) / 256, 256, 0, s_bin>>>(verts, Ntot);
    scan_kernel<<<1, 1024, 0, s_bin>>>();
    scatter_kernel<<<(Ntot + 255) / 256, 256, 0, s_bin>>>(verts, Ntot);
    cudaEventRecord(e_bin, s_bin);

    // s_mainA: phase 0 (cz<3) after slab a
    cudaStreamWaitEvent(s_mainA, e_Ta, 0);
    cudaStreamWaitEvent(s_mainA, e_prep, 0);
    cudaStreamWaitEvent(s_mainA, e_bin, 0);
    main_kernel<<<blocks, 256, 0, s_mainA>>>(verts, (float*)d_out, Ntot, 0);
    cudaEventRecord(e_mA, s_mainA);

    // s_bin (reused): phase 1 (cz<6) after slab b + prep
    cudaStreamWaitEvent(s_bin, e_Tb, 0);
    cudaStreamWaitEvent(s_bin, e_prep, 0);
    main_kernel<<<blocks, 256, 0, s_bin>>>(verts, (float*)d_out, Ntot, 1);
    cudaEventRecord(e_mB, s_bin);

    // s_prep (reused): phase 2 (cz<10) after slab c + binning
    cudaStreamWaitEvent(s_prep, e_Tc, 0);
    cudaStreamWaitEvent(s_prep, e_bin, 0);
    main_kernel<<<blocks, 256, 0, s_prep>>>(verts, (float*)d_out, Ntot, 2);
    cudaEventRecord(e_mC, s_prep);

    // stream 0: phase 3 after full transpose, then join
    cudaStreamWaitEvent(0, e_prep, 0);
    cudaStreamWaitEvent(0, e_bin, 0);
    main_kernel<<<blocks, 256>>>(verts, (float*)d_out, Ntot, 3);
    cudaStreamWaitEvent(0, e_mA, 0);
    cudaStreamWaitEvent(0, e_mB, 0);
    cudaStreamWaitEvent(0, e_mC, 0);
}